// round 1
// baseline (speedup 1.0000x reference)
#include <cuda_runtime.h>

typedef unsigned long long ull;

__device__ float d_qconst[13];

// ---------------------------------------------------------------------------
// Fold the fixed circuit into per-wire coefficients (runs once per launch).
// For each wire w: U_w = product of its random-layer gates (k % 4 == w, in
// order), M = U^dag Z U (Hermitian), then
//   z_w = c0 + c1*cos(a)cos(b) + c2*cos(a)sin(b) + c3*sin(a)
// with c0=(m00+m11)/2, c1=(m00-m11)/2, c2=Re(m01), c3=Im(m01).
// Stored pre-multiplied by head_w; d_qconst[12] = head_b + sum(head_w*c0).
// ---------------------------------------------------------------------------
__global__ void qconst_kernel(const float* __restrict__ rp,
                              const float* __restrict__ hw,
                              const float* __restrict__ hb) {
    if (blockIdx.x != 0 || threadIdx.x != 0) return;
    double Csum = (double)hb[0];
    for (int w = 0; w < 4; ++w) {
        double ur00 = 1, ui00 = 0, ur01 = 0, ui01 = 0;
        double ur10 = 0, ui10 = 0, ur11 = 1, ui11 = 0;
        for (int k = 0; k < 30; ++k) {
            if ((k & 3) != w) continue;
            double th = (double)rp[k];
            double c = cos(th * 0.5), s = sin(th * 0.5);
            double gr00, gi00, gr01, gi01, gr10, gi10, gr11, gi11;
            int g = k % 3;
            if (g == 0) {        // RX
                gr00 = c; gi00 = 0; gr01 = 0; gi01 = -s;
                gr10 = 0; gi10 = -s; gr11 = c; gi11 = 0;
            } else if (g == 1) { // RY
                gr00 = c; gi00 = 0; gr01 = -s; gi01 = 0;
                gr10 = s; gi10 = 0; gr11 = c; gi11 = 0;
            } else {             // RZ
                gr00 = c; gi00 = -s; gr01 = 0; gi01 = 0;
                gr10 = 0; gi10 = 0; gr11 = c; gi11 = s;
            }
            // U = G * U (complex 2x2)
            double nr00 = gr00*ur00 - gi00*ui00 + gr01*ur10 - gi01*ui10;
            double ni00 = gr00*ui00 + gi00*ur00 + gr01*ui10 + gi01*ur10;
            double nr01 = gr00*ur01 - gi00*ui01 + gr01*ur11 - gi01*ui11;
            double ni01 = gr00*ui01 + gi00*ur01 + gr01*ui11 + gi01*ur11;
            double nr10 = gr10*ur00 - gi10*ui00 + gr11*ur10 - gi11*ui10;
            double ni10 = gr10*ui00 + gi10*ur00 + gr11*ui10 + gi11*ur10;
            double nr11 = gr10*ur01 - gi10*ui01 + gr11*ur11 - gi11*ui11;
            double ni11 = gr10*ui01 + gi10*ur01 + gr11*ui11 + gi11*ur11;
            ur00 = nr00; ui00 = ni00; ur01 = nr01; ui01 = ni01;
            ur10 = nr10; ui10 = ni10; ur11 = nr11; ui11 = ni11;
        }
        double m00  = ur00*ur00 + ui00*ui00 - (ur10*ur10 + ui10*ui10);
        double m11  = ur01*ur01 + ui01*ui01 - (ur11*ur11 + ui11*ui11);
        double m01r = (ur00*ur01 + ui00*ui01) - (ur10*ur11 + ui10*ui11);
        double m01i = (ur00*ui01 - ui00*ur01) - (ur10*ui11 - ui10*ur11);
        double h = (double)hw[w];
        d_qconst[w * 3 + 0] = (float)(h * 0.5 * (m00 - m11));
        d_qconst[w * 3 + 1] = (float)(h * m01r);
        d_qconst[w * 3 + 2] = (float)(h * m01i);
        Csum += h * 0.5 * (m00 + m11);
    }
    d_qconst[12] = (float)Csum;
}

// ---------------------------------------------------------------------------
// f32x2 helpers (packed dual-fp32 ops, sm_103a)
// ---------------------------------------------------------------------------
__device__ __forceinline__ ull pack2(float lo, float hi) {
    ull r; asm("mov.b64 %0, {%1, %2};" : "=l"(r) : "f"(lo), "f"(hi)); return r;
}
__device__ __forceinline__ void unpack2(ull v, float& lo, float& hi) {
    asm("mov.b64 {%0, %1}, %2;" : "=f"(lo), "=f"(hi) : "l"(v));
}
__device__ __forceinline__ ull fma2(ull a, ull b, ull c) {
    ull d; asm("fma.rn.f32x2 %0, %1, %2, %3;" : "=l"(d) : "l"(a), "l"(b), "l"(c)); return d;
}
__device__ __forceinline__ ull add2(ull a, ull b) {
    ull d; asm("add.rn.f32x2 %0, %1, %2;" : "=l"(d) : "l"(a), "l"(b)); return d;
}

// ---------------------------------------------------------------------------
// Fused streaming kernel: warp-per-row, enc_w in registers (f32x2 packed),
// butterfly reduce, lane-parallel trig epilogue.
// ---------------------------------------------------------------------------
__global__ __launch_bounds__(256, 2)
void fused_kernel(const float4* __restrict__ x4,
                  const float4* __restrict__ w4,   // enc_w [8][256] as float4
                  const float* __restrict__ enc_b,
                  float* __restrict__ out,
                  int B) {
    const int lane = threadIdx.x & 31;
    const int warpId = (blockIdx.x * blockDim.x + threadIdx.x) >> 5;
    const int warpsTotal = (gridDim.x * blockDim.x) >> 5;

    // enc_w into registers: wreg[p][c][j] = (enc_w[2p][k], enc_w[2p+1][k]),
    // k = c*128 + 4*lane + j.  64 registers, loaded once (L2-resident).
    ull wreg[4][2][4];
#pragma unroll
    for (int p = 0; p < 4; ++p)
#pragma unroll
        for (int c = 0; c < 2; ++c) {
            float4 a = w4[(2 * p) * 64 + c * 32 + lane];
            float4 b = w4[(2 * p + 1) * 64 + c * 32 + lane];
            wreg[p][c][0] = pack2(a.x, b.x);
            wreg[p][c][1] = pack2(a.y, b.y);
            wreg[p][c][2] = pack2(a.z, b.z);
            wreg[p][c][3] = pack2(a.w, b.w);
        }

    const float eb = enc_b[lane & 7];
    const int wq = lane & 3;
    const float g1 = d_qconst[wq * 3 + 0];
    const float g2 = d_qconst[wq * 3 + 1];
    const float g3 = d_qconst[wq * 3 + 2];
    const float Cc = d_qconst[12];

    int row = warpId;
    if (row >= B) return;
    float4 xa = x4[row * 64 + lane];
    float4 xb = x4[row * 64 + 32 + lane];

    while (true) {
        const int nrow = row + warpsTotal;

        // 8 dot-products as 4 packed f32x2 accumulators
        ull acc[4] = {0ull, 0ull, 0ull, 0ull};
        {
            float xs[8] = {xa.x, xa.y, xa.z, xa.w, xb.x, xb.y, xb.z, xb.w};
#pragma unroll
            for (int q = 0; q < 8; ++q) {
                ull xx = pack2(xs[q], xs[q]);
                const int c = q >> 2, j = q & 3;
#pragma unroll
                for (int p = 0; p < 4; ++p)
                    acc[p] = fma2(xx, wreg[p][c][j], acc[p]);
            }
        }

        // prefetch next row's x behind the reduction/epilogue
        float4 na, nb;
        const bool more = (nrow < B);
        if (more) {
            na = x4[nrow * 64 + lane];
            nb = x4[nrow * 64 + 32 + lane];
        }

        // full butterfly reduce (every lane ends with all 8 dots)
#pragma unroll
        for (int d = 16; d >= 1; d >>= 1) {
#pragma unroll
            for (int p = 0; p < 4; ++p)
                acc[p] = add2(acc[p], __shfl_xor_sync(0xffffffffu, acc[p], d));
        }

        // epilogue spread over lanes: lane j handles angle j (j = lane & 7)
        const int j = lane & 7;
        ull sel = (j < 4) ? ((j < 2) ? acc[0] : acc[1])
                          : ((j < 6) ? acc[2] : acc[3]);
        float lo, hi;
        unpack2(sel, lo, hi);
        float dj = (j & 1) ? hi : lo;
        float t = dj + eb;
        // accurate-enough fast tanh: 1 - 2/(e^{2t}+1)
        float e = __expf(2.0f * t);
        float th = 1.0f - __fdividef(2.0f, e + 1.0f);
        float sn, cs;
        __sincosf(th, &sn, &cs);
        // lanes 0..3 pull partner (RY angle) trig from lanes 4..7
        float cb = __shfl_sync(0xffffffffu, cs, lane + 4);
        float sb = __shfl_sync(0xffffffffu, sn, lane + 4);
        float r = fmaf(cs, fmaf(g2, sb, g1 * cb), g3 * sn);
        r += __shfl_xor_sync(0xffffffffu, r, 1);
        r += __shfl_xor_sync(0xffffffffu, r, 2);
        if (lane == 0) out[row] = r + Cc;

        if (!more) break;
        xa = na; xb = nb; row = nrow;
    }
}

extern "C" void kernel_launch(void* const* d_in, const int* in_sizes, int n_in,
                              void* d_out, int out_size) {
    const float* x     = (const float*)d_in[0];
    const float* enc_w = (const float*)d_in[1];
    const float* enc_b = (const float*)d_in[2];
    const float* rp    = (const float*)d_in[3];
    const float* hw    = (const float*)d_in[4];
    const float* hb    = (const float*)d_in[5];
    float* out = (float*)d_out;

    const int B = in_sizes[0] / 256;  // F = 256

    qconst_kernel<<<1, 1>>>(rp, hw, hb);
    fused_kernel<<<1184, 256>>>((const float4*)x, (const float4*)enc_w,
                                enc_b, out, B);
}

// round 3
// speedup vs baseline: 1.8327x; 1.8327x over previous
#include <cuda_runtime.h>

typedef unsigned long long ull;

__device__ float d_qconst[13];

// ---------------------------------------------------------------------------
// Fold the fixed circuit into per-wire coefficients. Parallel over 4 wires,
// fp32 trig for gate angles (1-2 ulp), double HW-FMA for the matrix algebra.
//   z_w = c0 + c1*cos(a)cos(b) + c2*cos(a)sin(b) + c3*sin(a)
// Stored pre-multiplied by head_w; d_qconst[12] = head_b + sum(head_w*c0).
// ---------------------------------------------------------------------------
__global__ void qconst_kernel(const float* __restrict__ rp,
                              const float* __restrict__ hw,
                              const float* __restrict__ hb) {
    __shared__ double c0h[4];
    const int w = threadIdx.x;
    if (w < 4) {
        double ur00 = 1, ui00 = 0, ur01 = 0, ui01 = 0;
        double ur10 = 0, ui10 = 0, ur11 = 1, ui11 = 0;
        for (int k = w; k < 30; k += 4) {
            float sf, cf;
            __sincosf(0.0f, &sf, &cf);       // keep compiler honest (no-op)
            sincosf(rp[k] * 0.5f, &sf, &cf); // accurate fp32 trig
            double c = (double)cf, s = (double)sf;
            double gr00, gi00, gr01, gi01, gr10, gi10, gr11, gi11;
            int g = k % 3;
            if (g == 0) {        // RX
                gr00 = c; gi00 = 0; gr01 = 0; gi01 = -s;
                gr10 = 0; gi10 = -s; gr11 = c; gi11 = 0;
            } else if (g == 1) { // RY
                gr00 = c; gi00 = 0; gr01 = -s; gi01 = 0;
                gr10 = s; gi10 = 0; gr11 = c; gi11 = 0;
            } else {             // RZ
                gr00 = c; gi00 = -s; gr01 = 0; gi01 = 0;
                gr10 = 0; gi10 = 0; gr11 = c; gi11 = s;
            }
            double nr00 = gr00*ur00 - gi00*ui00 + gr01*ur10 - gi01*ui10;
            double ni00 = gr00*ui00 + gi00*ur00 + gr01*ui10 + gi01*ur10;
            double nr01 = gr00*ur01 - gi00*ui01 + gr01*ur11 - gi01*ui11;
            double ni01 = gr00*ui01 + gi00*ur01 + gr01*ui11 + gi01*ur11;
            double nr10 = gr10*ur00 - gi10*ui00 + gr11*ur10 - gi11*ui10;
            double ni10 = gr10*ui00 + gi10*ur00 + gr11*ui10 + gi11*ur10;
            double nr11 = gr10*ur01 - gi10*ui01 + gr11*ur11 - gi11*ui11;
            double ni11 = gr10*ui01 + gi10*ur01 + gr11*ui11 + gi11*ur11;
            ur00 = nr00; ui00 = ni00; ur01 = nr01; ui01 = ni01;
            ur10 = nr10; ui10 = ni10; ur11 = nr11; ui11 = ni11;
        }
        double m00  = ur00*ur00 + ui00*ui00 - (ur10*ur10 + ui10*ui10);
        double m11  = ur01*ur01 + ui01*ui01 - (ur11*ur11 + ui11*ui11);
        double m01r = (ur00*ur01 + ui00*ui01) - (ur10*ur11 + ui10*ui11);
        double m01i = (ur00*ui01 - ui00*ur01) - (ur10*ui11 - ui10*ur11);
        double h = (double)hw[w];
        d_qconst[w * 3 + 0] = (float)(h * 0.5 * (m00 - m11));
        d_qconst[w * 3 + 1] = (float)(h * m01r);
        d_qconst[w * 3 + 2] = (float)(h * m01i);
        c0h[w] = h * 0.5 * (m00 + m11);
    }
    __syncthreads();
    if (w == 0)
        d_qconst[12] = (float)((double)hb[0] + c0h[0] + c0h[1] + c0h[2] + c0h[3]);
}

// ---------------------------------------------------------------------------
// f32x2 helpers (packed dual-fp32 ops, sm_103a)
// ---------------------------------------------------------------------------
__device__ __forceinline__ ull pack2(float lo, float hi) {
    ull r; asm("mov.b64 %0, {%1, %2};" : "=l"(r) : "f"(lo), "f"(hi)); return r;
}
__device__ __forceinline__ void unpack2(ull v, float& lo, float& hi) {
    asm("mov.b64 {%0, %1}, %2;" : "=f"(lo), "=f"(hi) : "l"(v));
}
__device__ __forceinline__ ull fma2(ull a, ull b, ull c) {
    ull d; asm("fma.rn.f32x2 %0, %1, %2, %3;" : "=l"(d) : "l"(a), "l"(b), "l"(c)); return d;
}
__device__ __forceinline__ ull add2(ull a, ull b) {
    ull d; asm("add.rn.f32x2 %0, %1, %2;" : "=l"(d) : "l"(a), "l"(b)); return d;
}

// ---------------------------------------------------------------------------
// Fused streaming kernel: warp-per-row, enc_w in registers (f32x2 packed),
// FOLDING reduce (4 accs -> 2 -> 1 -> butterfly -> redistribute), then
// lane-parallel trig epilogue.
// ---------------------------------------------------------------------------
__global__ __launch_bounds__(256, 2)
void fused_kernel(const float4* __restrict__ x4,
                  const float4* __restrict__ w4,   // enc_w [8][256] as float4
                  const float* __restrict__ enc_b,
                  float* __restrict__ out,
                  int B) {
    const int lane = threadIdx.x & 31;
    const int warpId = (blockIdx.x * blockDim.x + threadIdx.x) >> 5;
    const int warpsTotal = (gridDim.x * blockDim.x) >> 5;

    // enc_w into registers: wreg[p][c][j] = (enc_w[2p][k], enc_w[2p+1][k]),
    // k = c*128 + 4*lane + j.
    ull wreg[4][2][4];
#pragma unroll
    for (int p = 0; p < 4; ++p)
#pragma unroll
        for (int c = 0; c < 2; ++c) {
            float4 a = w4[(2 * p) * 64 + c * 32 + lane];
            float4 b = w4[(2 * p + 1) * 64 + c * 32 + lane];
            wreg[p][c][0] = pack2(a.x, b.x);
            wreg[p][c][1] = pack2(a.y, b.y);
            wreg[p][c][2] = pack2(a.z, b.z);
            wreg[p][c][3] = pack2(a.w, b.w);
        }

    const float eb = enc_b[lane & 7];
    const int wq = lane & 3;
    const float g1 = d_qconst[wq * 3 + 0];
    const float g2 = d_qconst[wq * 3 + 1];
    const float g3 = d_qconst[wq * 3 + 2];
    const float Cc = d_qconst[12];

    int row = warpId;
    if (row >= B) return;
    float4 xa = x4[row * 64 + lane];
    float4 xb = x4[row * 64 + 32 + lane];

    while (true) {
        const int nrow = row + warpsTotal;

        // 8 dot-products as 4 packed f32x2 accumulators
        ull acc[4] = {0ull, 0ull, 0ull, 0ull};
        {
            float xs[8] = {xa.x, xa.y, xa.z, xa.w, xb.x, xb.y, xb.z, xb.w};
#pragma unroll
            for (int q = 0; q < 8; ++q) {
                ull xx = pack2(xs[q], xs[q]);
                const int c = q >> 2, j = q & 3;
#pragma unroll
                for (int p = 0; p < 4; ++p)
                    acc[p] = fma2(xx, wreg[p][c][j], acc[p]);
            }
        }

        // prefetch next row's x behind the reduction/epilogue
        float4 na, nb;
        const bool more = (nrow < B);
        if (more) {
            na = x4[nrow * 64 + lane];
            nb = x4[nrow * 64 + 32 + lane];
        }

        // ---- folding reduce ----
        // Level A (xor 16): fold 4 accs -> 2.  Low half keeps outputs 0-3,
        // high half keeps outputs 4-7.
        ull lo0 = (lane & 16) ? acc[2] : acc[0];
        ull hi0 = (lane & 16) ? acc[0] : acc[2];
        lo0 = add2(lo0, __shfl_xor_sync(0xffffffffu, hi0, 16));
        ull lo1 = (lane & 16) ? acc[3] : acc[1];
        ull hi1 = (lane & 16) ? acc[1] : acc[3];
        lo1 = add2(lo1, __shfl_xor_sync(0xffffffffu, hi1, 16));
        // Level B (xor 8): fold 2 -> 1. Group g=(lane>>3)&3 holds outputs (2g,2g+1).
        ull lo = (lane & 8) ? lo1 : lo0;
        ull hi = (lane & 8) ? lo0 : lo1;
        lo = add2(lo, __shfl_xor_sync(0xffffffffu, hi, 8));
        // Level C: butterfly xor 4,2,1 on a single ull -> full sums.
        lo = add2(lo, __shfl_xor_sync(0xffffffffu, lo, 4));
        lo = add2(lo, __shfl_xor_sync(0xffffffffu, lo, 2));
        lo = add2(lo, __shfl_xor_sync(0xffffffffu, lo, 1));
        // Redistribute: lane j (= lane&7) needs output j, held by group j>>1.
        ull d = __shfl_sync(0xffffffffu, lo, (lane & 6) << 2);

        // ---- epilogue: lane j handles angle j ----
        float dlo, dhi;
        unpack2(d, dlo, dhi);
        float dj = (lane & 1) ? dhi : dlo;
        float t = dj + eb;
        // fast tanh: 1 - 2/(e^{2t}+1)
        float e = __expf(2.0f * t);
        float th = 1.0f - __fdividef(2.0f, e + 1.0f);
        float sn, cs;
        __sincosf(th, &sn, &cs);
        // lanes 0..3 pull partner (RY angle) trig from lanes 4..7
        float cb = __shfl_sync(0xffffffffu, cs, lane + 4);
        float sb = __shfl_sync(0xffffffffu, sn, lane + 4);
        float r = fmaf(cs, fmaf(g2, sb, g1 * cb), g3 * sn);
        r += __shfl_xor_sync(0xffffffffu, r, 1);
        r += __shfl_xor_sync(0xffffffffu, r, 2);
        if (lane == 0) out[row] = r + Cc;

        if (!more) break;
        xa = na; xb = nb; row = nrow;
    }
}

extern "C" void kernel_launch(void* const* d_in, const int* in_sizes, int n_in,
                              void* d_out, int out_size) {
    const float* x     = (const float*)d_in[0];
    const float* enc_w = (const float*)d_in[1];
    const float* enc_b = (const float*)d_in[2];
    const float* rp    = (const float*)d_in[3];
    const float* hw    = (const float*)d_in[4];
    const float* hb    = (const float*)d_in[5];
    float* out = (float*)d_out;

    const int B = in_sizes[0] / 256;  // F = 256

    qconst_kernel<<<1, 32>>>(rp, hw, hb);
    fused_kernel<<<1184, 256>>>((const float4*)x, (const float4*)enc_w,
                                enc_b, out, B);
}

// round 4
// speedup vs baseline: 2.5218x; 1.3760x over previous
#include <cuda_runtime.h>

typedef unsigned long long ull;

// ---------------------------------------------------------------------------
// f32x2 helpers (packed dual-fp32 ops, sm_103a)
// ---------------------------------------------------------------------------
__device__ __forceinline__ ull pack2(float lo, float hi) {
    ull r; asm("mov.b64 %0, {%1, %2};" : "=l"(r) : "f"(lo), "f"(hi)); return r;
}
__device__ __forceinline__ void unpack2(ull v, float& lo, float& hi) {
    asm("mov.b64 {%0, %1}, %2;" : "=f"(lo), "=f"(hi) : "l"(v));
}
__device__ __forceinline__ ull fma2(ull a, ull b, ull c) {
    ull d; asm("fma.rn.f32x2 %0, %1, %2, %3;" : "=l"(d) : "l"(a), "l"(b), "l"(c)); return d;
}
__device__ __forceinline__ ull add2(ull a, ull b) {
    ull d; asm("add.rn.f32x2 %0, %1, %2;" : "=l"(d) : "l"(a), "l"(b)); return d;
}

// ---------------------------------------------------------------------------
// Single fused kernel.
//  * Per-warp preamble folds the fixed 30-gate circuit into per-wire coeffs
//    (lane w = lane&3 computes wire w -> exactly the lane that consumes it).
//  * Main loop: 2 rows / warp / iteration, enc_w in registers (f32x2),
//    combined folding reduce (row0 -> lanes 0-15, row1 -> lanes 16-31),
//    single shared trig epilogue for both rows.
// ---------------------------------------------------------------------------
__global__ __launch_bounds__(256, 2)
void fused_kernel(const float4* __restrict__ x4,
                  const float4* __restrict__ w4,   // enc_w [8][256] as float4
                  const float* __restrict__ enc_b,
                  const float* __restrict__ rp,
                  const float* __restrict__ hw,
                  const float* __restrict__ hb,
                  float* __restrict__ out,
                  int B) {
    const int lane = threadIdx.x & 31;
    const int warpId = (blockIdx.x * blockDim.x + threadIdx.x) >> 5;
    const int warpsTotal = (gridDim.x * blockDim.x) >> 5;

    // ---- enc_w into registers (loads issue first; latency hidden by the
    //      constant-folding preamble below) ----
    // wreg[p][c][j] = (enc_w[2p][k], enc_w[2p+1][k]), k = c*128 + 4*lane + j.
    ull wreg[4][2][4];
#pragma unroll
    for (int p = 0; p < 4; ++p)
#pragma unroll
        for (int c = 0; c < 2; ++c) {
            float4 a = w4[(2 * p) * 64 + c * 32 + lane];
            float4 b = w4[(2 * p + 1) * 64 + c * 32 + lane];
            wreg[p][c][0] = pack2(a.x, b.x);
            wreg[p][c][1] = pack2(a.y, b.y);
            wreg[p][c][2] = pack2(a.z, b.z);
            wreg[p][c][3] = pack2(a.w, b.w);
        }

    // ---- fold fixed circuit: wire w = lane&3, fp32 (error ~1e-6 << 1e-3) ----
    // U_w = prod of gates k (k%4==w); M = U^dag Z U;
    // z_w = c0 + c1*cos(a)cos(b) + c2*cos(a)sin(b) + c3*sin(a).
    float g1, g2, g3, Cc;
    {
        const int w = lane & 3;
        float ur00 = 1.f, ui00 = 0.f, ur01 = 0.f, ui01 = 0.f;
        float ur10 = 0.f, ui10 = 0.f, ur11 = 1.f, ui11 = 0.f;
        for (int k = w; k < 30; k += 4) {
            float s, c;
            __sincosf(rp[k] * 0.5f, &s, &c);
            const int g = k % 3;
            // branchless gate matrix; gr00 = gr11 = c
            const float gi01 = (g == 0) ? -s : 0.f;  // RX
            const float gi10 = (g == 0) ? -s : 0.f;
            const float gr01 = (g == 1) ? -s : 0.f;  // RY
            const float gr10 = (g == 1) ?  s : 0.f;
            const float gi00 = (g == 2) ? -s : 0.f;  // RZ
            const float gi11 = (g == 2) ?  s : 0.f;
            const float nr00 = c*ur00 - gi00*ui00 + gr01*ur10 - gi01*ui10;
            const float ni00 = c*ui00 + gi00*ur00 + gr01*ui10 + gi01*ur10;
            const float nr01 = c*ur01 - gi00*ui01 + gr01*ur11 - gi01*ui11;
            const float ni01 = c*ui01 + gi00*ur01 + gr01*ui11 + gi01*ur11;
            const float nr10 = gr10*ur00 - gi10*ui00 + c*ur10 - gi11*ui10;
            const float ni10 = gr10*ui00 + gi10*ur00 + c*ui10 + gi11*ur10;
            const float nr11 = gr10*ur01 - gi10*ui01 + c*ur11 - gi11*ui11;
            const float ni11 = gr10*ui01 + gi10*ur01 + c*ui11 + gi11*ur11;
            ur00 = nr00; ui00 = ni00; ur01 = nr01; ui01 = ni01;
            ur10 = nr10; ui10 = ni10; ur11 = nr11; ui11 = ni11;
        }
        const float m00  = ur00*ur00 + ui00*ui00 - (ur10*ur10 + ui10*ui10);
        const float m11  = ur01*ur01 + ui01*ui01 - (ur11*ur11 + ui11*ui11);
        const float m01r = (ur00*ur01 + ui00*ui01) - (ur10*ur11 + ui10*ui11);
        const float m01i = (ur00*ui01 - ui00*ur01) - (ur10*ui11 - ui10*ur11);
        const float h = hw[w];
        g1 = h * 0.5f * (m00 - m11);
        g2 = h * m01r;
        g3 = h * m01i;
        float c0w = h * 0.5f * (m00 + m11);
        c0w += __shfl_xor_sync(0xffffffffu, c0w, 1);
        c0w += __shfl_xor_sync(0xffffffffu, c0w, 2);
        Cc = hb[0] + c0w;
    }

    const float eb = enc_b[lane & 7];

    const int nPairs = B >> 1;
    for (int pair = warpId; pair < nPairs; pair += warpsTotal) {
        const int r0 = pair * 2;
        const int r1 = r0 + 1;

        // front-batched loads: MLP = 4 per warp
        const float4 x0a = x4[r0 * 64 + lane];
        const float4 x0b = x4[r0 * 64 + 32 + lane];
        const float4 x1a = x4[r1 * 64 + lane];
        const float4 x1b = x4[r1 * 64 + 32 + lane];

        // 8 dot-products per row as 4 packed f32x2 accumulators, 2 rows
        ull acc0[4] = {0ull, 0ull, 0ull, 0ull};
        ull acc1[4] = {0ull, 0ull, 0ull, 0ull};
        {
            const float xs0[8] = {x0a.x, x0a.y, x0a.z, x0a.w, x0b.x, x0b.y, x0b.z, x0b.w};
            const float xs1[8] = {x1a.x, x1a.y, x1a.z, x1a.w, x1b.x, x1b.y, x1b.z, x1b.w};
#pragma unroll
            for (int q = 0; q < 8; ++q) {
                const int c = q >> 2, j = q & 3;
                const ull xx0 = pack2(xs0[q], xs0[q]);
                const ull xx1 = pack2(xs1[q], xs1[q]);
#pragma unroll
                for (int p = 0; p < 4; ++p) {
                    acc0[p] = fma2(xx0, wreg[p][c][j], acc0[p]);
                    acc1[p] = fma2(xx1, wreg[p][c][j], acc1[p]);
                }
            }
        }

        // ---- combined folding reduce ----
        // xor16: row0 -> lanes 0-15, row1 -> lanes 16-31
        ull m[4];
#pragma unroll
        for (int p = 0; p < 4; ++p) {
            const ull mine  = (lane & 16) ? acc1[p] : acc0[p];
            const ull other = (lane & 16) ? acc0[p] : acc1[p];
            m[p] = add2(mine, __shfl_xor_sync(0xffffffffu, other, 16));
        }
        // xor8: fold 4 -> 2 (bit3=0 keeps outputs 0-3, bit3=1 keeps 4-7)
        ull ra, rb;
        {
            const ull a = (lane & 8) ? m[2] : m[0];
            const ull b = (lane & 8) ? m[0] : m[2];
            ra = add2(a, __shfl_xor_sync(0xffffffffu, b, 8));
            const ull cA = (lane & 8) ? m[3] : m[1];
            const ull dA = (lane & 8) ? m[1] : m[3];
            rb = add2(cA, __shfl_xor_sync(0xffffffffu, dA, 8));
        }
        // xor4: fold 2 -> 1
        ull s;
        {
            const ull a = (lane & 4) ? rb : ra;
            const ull b = (lane & 4) ? ra : rb;
            s = add2(a, __shfl_xor_sync(0xffffffffu, b, 4));
        }
        // butterfly over remaining lane bits 1,0
        s = add2(s, __shfl_xor_sync(0xffffffffu, s, 2));
        s = add2(s, __shfl_xor_sync(0xffffffffu, s, 1));
        // redistribute: lane L (row = bit4, j = L&7) reads pair q'=j>>1 from
        // source lane (L&16) | (q'<<2)
        const ull d = __shfl_sync(0xffffffffu, s, (lane & 16) | ((lane & 6) << 1));

        // ---- shared epilogue: lanes 0-7 => row0, lanes 16-23 => row1 ----
        float dlo, dhi;
        unpack2(d, dlo, dhi);
        const float dj = (lane & 1) ? dhi : dlo;
        const float t = dj + eb;
        // fast tanh: 1 - 2/(e^{2t}+1)
        const float e = __expf(2.0f * t);
        const float th = 1.0f - __fdividef(2.0f, e + 1.0f);
        float sn, cs;
        __sincosf(th, &sn, &cs);
        // RX-angle lanes (j<4) pull RY-angle trig from lane+4 (same 16-half)
        const float cb = __shfl_sync(0xffffffffu, cs, lane + 4);
        const float sb = __shfl_sync(0xffffffffu, sn, lane + 4);
        float r = fmaf(cs, fmaf(g2, sb, g1 * cb), g3 * sn);
        r += __shfl_xor_sync(0xffffffffu, r, 1);
        r += __shfl_xor_sync(0xffffffffu, r, 2);
        if ((lane & 15) == 0)
            out[(lane & 16) ? r1 : r0] = r + Cc;
    }
}

extern "C" void kernel_launch(void* const* d_in, const int* in_sizes, int n_in,
                              void* d_out, int out_size) {
    const float* x     = (const float*)d_in[0];
    const float* enc_w = (const float*)d_in[1];
    const float* enc_b = (const float*)d_in[2];
    const float* rp    = (const float*)d_in[3];
    const float* hw    = (const float*)d_in[4];
    const float* hb    = (const float*)d_in[5];
    float* out = (float*)d_out;

    const int B = in_sizes[0] / 256;  // F = 256

    fused_kernel<<<296, 256>>>((const float4*)x, (const float4*)enc_w,
                               enc_b, rp, hw, hb, out, B);
}

// round 5
// speedup vs baseline: 3.3843x; 1.3420x over previous
#include <cuda_runtime.h>

typedef unsigned long long ull;

// ---------------------------------------------------------------------------
// f32x2 helpers (packed dual-fp32 ops, sm_103a)
// ---------------------------------------------------------------------------
__device__ __forceinline__ ull pack2(float lo, float hi) {
    ull r; asm("mov.b64 %0, {%1, %2};" : "=l"(r) : "f"(lo), "f"(hi)); return r;
}
__device__ __forceinline__ void unpack2(ull v, float& lo, float& hi) {
    asm("mov.b64 {%0, %1}, %2;" : "=f"(lo), "=f"(hi) : "l"(v));
}
__device__ __forceinline__ ull fma2(ull a, ull b, ull c) {
    ull d; asm("fma.rn.f32x2 %0, %1, %2, %3;" : "=l"(d) : "l"(a), "l"(b), "l"(c)); return d;
}
__device__ __forceinline__ ull add2(ull a, ull b) {
    ull d; asm("add.rn.f32x2 %0, %1, %2;" : "=l"(d) : "l"(a), "l"(b)); return d;
}

#define CP_ASYNC16(dst_u32, src_ptr) \
    asm volatile("cp.async.cg.shared.global [%0], [%1], 16;" \
                 :: "r"(dst_u32), "l"(src_ptr) : "memory")
#define CP_COMMIT() asm volatile("cp.async.commit_group;" ::: "memory")
#define CP_WAIT1()  asm volatile("cp.async.wait_group 1;"  ::: "memory")

// ---------------------------------------------------------------------------
// Single fused kernel.
//  * Per-warp preamble folds the fixed 30-gate circuit into per-wire coeffs.
//  * Main loop: 2 rows / warp / iteration; x streamed through a 3-stage
//    cp.async SMEM ring (distance-2 prefetch, zero register cost);
//    enc_w in registers (f32x2); combined folding reduce; shared trig
//    epilogue for both rows.
// ---------------------------------------------------------------------------
__global__ __launch_bounds__(256, 2)
void fused_kernel(const float4* __restrict__ x4,
                  const float4* __restrict__ w4,   // enc_w [8][256] as float4
                  const float* __restrict__ enc_b,
                  const float* __restrict__ rp,
                  const float* __restrict__ hw,
                  const float* __restrict__ hb,
                  float* __restrict__ out,
                  int B) {
    __shared__ float4 buf[3][8][128];   // 49152 B: 3 stages x 8 warps x 2KB

    const int lane = threadIdx.x & 31;
    const int wIn  = threadIdx.x >> 5;
    const int warpId = (blockIdx.x * blockDim.x + threadIdx.x) >> 5;
    const int W = (gridDim.x * blockDim.x) >> 5;

    // smem byte addresses of this lane's 4 slots, per stage
    unsigned sb[3];
#pragma unroll
    for (int s = 0; s < 3; ++s)
        sb[s] = (unsigned)__cvta_generic_to_shared(&buf[s][wIn][lane]);

    const int nPairs = B >> 1;

    // ---- pipeline prologue: issue pairs warpId (stage0), warpId+W (stage1)
    {
        const int p0 = warpId;
        if (p0 < nPairs) {
            const float4* g = x4 + (size_t)p0 * 128 + lane;
#pragma unroll
            for (int j = 0; j < 4; ++j) CP_ASYNC16(sb[0] + j * 512, g + j * 32);
        }
        CP_COMMIT();
        const int p1 = warpId + W;
        if (p1 < nPairs) {
            const float4* g = x4 + (size_t)p1 * 128 + lane;
#pragma unroll
            for (int j = 0; j < 4; ++j) CP_ASYNC16(sb[1] + j * 512, g + j * 32);
        }
        CP_COMMIT();
    }

    // ---- enc_w into registers (latency hidden by constant folding below) --
    // wreg[p][c][j] = (enc_w[2p][k], enc_w[2p+1][k]), k = c*128 + 4*lane + j.
    ull wreg[4][2][4];
#pragma unroll
    for (int p = 0; p < 4; ++p)
#pragma unroll
        for (int c = 0; c < 2; ++c) {
            float4 a = w4[(2 * p) * 64 + c * 32 + lane];
            float4 b = w4[(2 * p + 1) * 64 + c * 32 + lane];
            wreg[p][c][0] = pack2(a.x, b.x);
            wreg[p][c][1] = pack2(a.y, b.y);
            wreg[p][c][2] = pack2(a.z, b.z);
            wreg[p][c][3] = pack2(a.w, b.w);
        }

    // ---- fold fixed circuit: wire w = lane&3, fp32 -----------------------
    float g1, g2, g3, Cc;
    {
        const int w = lane & 3;
        float ur00 = 1.f, ui00 = 0.f, ur01 = 0.f, ui01 = 0.f;
        float ur10 = 0.f, ui10 = 0.f, ur11 = 1.f, ui11 = 0.f;
        for (int k = w; k < 30; k += 4) {
            float s, c;
            __sincosf(rp[k] * 0.5f, &s, &c);
            const int g = k % 3;
            const float gi01 = (g == 0) ? -s : 0.f;  // RX
            const float gi10 = (g == 0) ? -s : 0.f;
            const float gr01 = (g == 1) ? -s : 0.f;  // RY
            const float gr10 = (g == 1) ?  s : 0.f;
            const float gi00 = (g == 2) ? -s : 0.f;  // RZ
            const float gi11 = (g == 2) ?  s : 0.f;
            const float nr00 = c*ur00 - gi00*ui00 + gr01*ur10 - gi01*ui10;
            const float ni00 = c*ui00 + gi00*ur00 + gr01*ui10 + gi01*ur10;
            const float nr01 = c*ur01 - gi00*ui01 + gr01*ur11 - gi01*ui11;
            const float ni01 = c*ui01 + gi00*ur01 + gr01*ui11 + gi01*ur11;
            const float nr10 = gr10*ur00 - gi10*ui00 + c*ur10 - gi11*ui10;
            const float ni10 = gr10*ui00 + gi10*ur00 + c*ui10 + gi11*ur10;
            const float nr11 = gr10*ur01 - gi10*ui01 + c*ur11 - gi11*ui11;
            const float ni11 = gr10*ui01 + gi10*ur01 + c*ui11 + gi11*ur11;
            ur00 = nr00; ui00 = ni00; ur01 = nr01; ui01 = ni01;
            ur10 = nr10; ui10 = ni10; ur11 = nr11; ui11 = ni11;
        }
        const float m00  = ur00*ur00 + ui00*ui00 - (ur10*ur10 + ui10*ui10);
        const float m11  = ur01*ur01 + ui01*ui01 - (ur11*ur11 + ui11*ui11);
        const float m01r = (ur00*ur01 + ui00*ui01) - (ur10*ur11 + ui10*ui11);
        const float m01i = (ur00*ui01 - ui00*ur01) - (ur10*ui11 - ui10*ur11);
        const float h = hw[w];
        g1 = h * 0.5f * (m00 - m11);
        g2 = h * m01r;
        g3 = h * m01i;
        float c0w = h * 0.5f * (m00 + m11);
        c0w += __shfl_xor_sync(0xffffffffu, c0w, 1);
        c0w += __shfl_xor_sync(0xffffffffu, c0w, 2);
        Cc = hb[0] + c0w;
    }

    const float eb = enc_b[lane & 7];

    int stage = 0;
    for (int pair = warpId; pair < nPairs; pair += W) {
        // wait until the current stage's data has landed
        CP_WAIT1();

        // read this lane's 4 slots (same bytes this lane cp.async'd)
        const float4 x0a = buf[stage][wIn][lane];
        const float4 x0b = buf[stage][wIn][32 + lane];
        const float4 x1a = buf[stage][wIn][64 + lane];
        const float4 x1b = buf[stage][wIn][96 + lane];

        // issue prefetch for pair+2W into the stage read LAST iteration
        {
            const int pf = pair + 2 * W;
            const int fs = (stage + 2 >= 3) ? stage - 1 : stage + 2;
            if (pf < nPairs) {
                const float4* g = x4 + (size_t)pf * 128 + lane;
#pragma unroll
                for (int j = 0; j < 4; ++j) CP_ASYNC16(sb[fs] + j * 512, g + j * 32);
            }
            CP_COMMIT();
        }

        // 8 dot-products per row as 4 packed f32x2 accumulators, 2 rows
        ull acc0[4] = {0ull, 0ull, 0ull, 0ull};
        ull acc1[4] = {0ull, 0ull, 0ull, 0ull};
        {
            const float xs0[8] = {x0a.x, x0a.y, x0a.z, x0a.w, x0b.x, x0b.y, x0b.z, x0b.w};
            const float xs1[8] = {x1a.x, x1a.y, x1a.z, x1a.w, x1b.x, x1b.y, x1b.z, x1b.w};
#pragma unroll
            for (int q = 0; q < 8; ++q) {
                const int c = q >> 2, j = q & 3;
                const ull xx0 = pack2(xs0[q], xs0[q]);
                const ull xx1 = pack2(xs1[q], xs1[q]);
#pragma unroll
                for (int p = 0; p < 4; ++p) {
                    acc0[p] = fma2(xx0, wreg[p][c][j], acc0[p]);
                    acc1[p] = fma2(xx1, wreg[p][c][j], acc1[p]);
                }
            }
        }

        // ---- combined folding reduce ----
        // xor16: row0 -> lanes 0-15, row1 -> lanes 16-31
        ull m[4];
#pragma unroll
        for (int p = 0; p < 4; ++p) {
            const ull mine  = (lane & 16) ? acc1[p] : acc0[p];
            const ull other = (lane & 16) ? acc0[p] : acc1[p];
            m[p] = add2(mine, __shfl_xor_sync(0xffffffffu, other, 16));
        }
        // xor8: fold 4 -> 2
        ull ra, rb;
        {
            const ull a = (lane & 8) ? m[2] : m[0];
            const ull b = (lane & 8) ? m[0] : m[2];
            ra = add2(a, __shfl_xor_sync(0xffffffffu, b, 8));
            const ull cA = (lane & 8) ? m[3] : m[1];
            const ull dA = (lane & 8) ? m[1] : m[3];
            rb = add2(cA, __shfl_xor_sync(0xffffffffu, dA, 8));
        }
        // xor4: fold 2 -> 1
        ull s;
        {
            const ull a = (lane & 4) ? rb : ra;
            const ull b = (lane & 4) ? ra : rb;
            s = add2(a, __shfl_xor_sync(0xffffffffu, b, 4));
        }
        s = add2(s, __shfl_xor_sync(0xffffffffu, s, 2));
        s = add2(s, __shfl_xor_sync(0xffffffffu, s, 1));
        // redistribute: lane L (row = bit4, j = L&7) reads from
        // source lane (L&16) | ((L&6)<<1)
        const ull d = __shfl_sync(0xffffffffu, s, (lane & 16) | ((lane & 6) << 1));

        // ---- shared epilogue: lanes 0-7 => row0, lanes 16-23 => row1 ----
        float dlo, dhi;
        unpack2(d, dlo, dhi);
        const float dj = (lane & 1) ? dhi : dlo;
        const float t = dj + eb;
        const float e = __expf(2.0f * t);              // tanh = 1 - 2/(e^2t+1)
        const float th = 1.0f - __fdividef(2.0f, e + 1.0f);
        float sn, cs;
        __sincosf(th, &sn, &cs);
        const float cb = __shfl_sync(0xffffffffu, cs, lane + 4);
        const float sb2 = __shfl_sync(0xffffffffu, sn, lane + 4);
        float r = fmaf(cs, fmaf(g2, sb2, g1 * cb), g3 * sn);
        r += __shfl_xor_sync(0xffffffffu, r, 1);
        r += __shfl_xor_sync(0xffffffffu, r, 2);
        if ((lane & 15) == 0)
            out[2 * pair + ((lane >> 4) & 1)] = r + Cc;

        stage = (stage + 1 >= 3) ? 0 : stage + 1;
    }
}

extern "C" void kernel_launch(void* const* d_in, const int* in_sizes, int n_in,
                              void* d_out, int out_size) {
    const float* x     = (const float*)d_in[0];
    const float* enc_w = (const float*)d_in[1];
    const float* enc_b = (const float*)d_in[2];
    const float* rp    = (const float*)d_in[3];
    const float* hw    = (const float*)d_in[4];
    const float* hb    = (const float*)d_in[5];
    float* out = (float*)d_out;

    const int B = in_sizes[0] / 256;  // F = 256

    fused_kernel<<<296, 256>>>((const float4*)x, (const float4*)enc_w,
                               enc_b, rp, hw, hb, out, B);
}

// round 6
// speedup vs baseline: 3.4980x; 1.0336x over previous
#include <cuda_runtime.h>

typedef unsigned long long ull;

// ---------------------------------------------------------------------------
// f32x2 helpers (packed dual-fp32 ops, sm_103a)
// ---------------------------------------------------------------------------
__device__ __forceinline__ ull pack2(float lo, float hi) {
    ull r; asm("mov.b64 %0, {%1, %2};" : "=l"(r) : "f"(lo), "f"(hi)); return r;
}
__device__ __forceinline__ void unpack2(ull v, float& lo, float& hi) {
    asm("mov.b64 {%0, %1}, %2;" : "=f"(lo), "=f"(hi) : "l"(v));
}
__device__ __forceinline__ ull fma2(ull a, ull b, ull c) {
    ull d; asm("fma.rn.f32x2 %0, %1, %2, %3;" : "=l"(d) : "l"(a), "l"(b), "l"(c)); return d;
}
__device__ __forceinline__ ull add2(ull a, ull b) {
    ull d; asm("add.rn.f32x2 %0, %1, %2;" : "=l"(d) : "l"(a), "l"(b)); return d;
}

#define CP_ASYNC16(dst_u32, src_ptr) \
    asm volatile("cp.async.cg.shared.global [%0], [%1], 16;" \
                 :: "r"(dst_u32), "l"(src_ptr) : "memory")
#define CP_COMMIT() asm volatile("cp.async.commit_group;" ::: "memory")
#define CP_WAIT1()  asm volatile("cp.async.wait_group 1;"  ::: "memory")

// ---------------------------------------------------------------------------
// Single fused kernel, 4 rows / warp / iteration.
//  * x streamed via 3-stage cp.async SMEM ring (4KB/warp/stage, distance-2).
//  * enc_w in registers (f32x2).  Bit-fold reduce over lane bits
//    {8,16,4,2,1} -> lane L ends holding dot d_{L&7} of row L>>3 with NO
//    redistribution shuffle.  One shared trig epilogue serves all 4 rows
//    (every lane does useful MUFU work).
// ---------------------------------------------------------------------------
__global__ __launch_bounds__(256, 2)
void fused_kernel(const float4* __restrict__ x4,
                  const float4* __restrict__ w4,   // enc_w [8][256] as float4
                  const float* __restrict__ enc_b,
                  const float* __restrict__ rp,
                  const float* __restrict__ hw,
                  const float* __restrict__ hb,
                  float* __restrict__ out,
                  int B) {
    extern __shared__ float4 dynbuf[];   // 3 stages x 8 warps x 256 float4 = 96KB

    const int lane = threadIdx.x & 31;
    const int wIn  = threadIdx.x >> 5;
    const int warpId = (blockIdx.x * blockDim.x + threadIdx.x) >> 5;
    const int W = (gridDim.x * blockDim.x) >> 5;

    // byte address of this lane's slot 0 in stage 0; stage s at +s*32768
    const unsigned sbase =
        (unsigned)__cvta_generic_to_shared(dynbuf + (size_t)wIn * 256 + lane);

    const int nQuads = B >> 2;   // 4 rows (1KB each) per quad

    // ---- prologue: issue quads warpId (stage0), warpId+W (stage1) ----
#pragma unroll
    for (int i = 0; i < 2; ++i) {
        const int q = warpId + i * W;
        if (q < nQuads) {
            const float4* g = x4 + (size_t)q * 256 + lane;
            const unsigned d = sbase + (unsigned)i * 32768u;
#pragma unroll
            for (int j = 0; j < 8; ++j) CP_ASYNC16(d + j * 512u, g + j * 32);
        }
        CP_COMMIT();
    }

    // ---- enc_w into registers (latency hidden by constant folding below) --
    // wreg[p][c][j] = (enc_w[2p][k], enc_w[2p+1][k]), k = c*128 + 4*lane + j.
    ull wreg[4][2][4];
#pragma unroll
    for (int p = 0; p < 4; ++p)
#pragma unroll
        for (int c = 0; c < 2; ++c) {
            float4 a = w4[(2 * p) * 64 + c * 32 + lane];
            float4 b = w4[(2 * p + 1) * 64 + c * 32 + lane];
            wreg[p][c][0] = pack2(a.x, b.x);
            wreg[p][c][1] = pack2(a.y, b.y);
            wreg[p][c][2] = pack2(a.z, b.z);
            wreg[p][c][3] = pack2(a.w, b.w);
        }

    // ---- fold fixed circuit: wire w = lane&3, fp32 -----------------------
    float g1, g2, g3, Cc;
    {
        const int w = lane & 3;
        float ur00 = 1.f, ui00 = 0.f, ur01 = 0.f, ui01 = 0.f;
        float ur10 = 0.f, ui10 = 0.f, ur11 = 1.f, ui11 = 0.f;
        for (int k = w; k < 30; k += 4) {
            float s, c;
            __sincosf(rp[k] * 0.5f, &s, &c);
            const int g = k % 3;
            const float gi01 = (g == 0) ? -s : 0.f;  // RX
            const float gi10 = (g == 0) ? -s : 0.f;
            const float gr01 = (g == 1) ? -s : 0.f;  // RY
            const float gr10 = (g == 1) ?  s : 0.f;
            const float gi00 = (g == 2) ? -s : 0.f;  // RZ
            const float gi11 = (g == 2) ?  s : 0.f;
            const float nr00 = c*ur00 - gi00*ui00 + gr01*ur10 - gi01*ui10;
            const float ni00 = c*ui00 + gi00*ur00 + gr01*ui10 + gi01*ur10;
            const float nr01 = c*ur01 - gi00*ui01 + gr01*ur11 - gi01*ui11;
            const float ni01 = c*ui01 + gi00*ur01 + gr01*ui11 + gi01*ur11;
            const float nr10 = gr10*ur00 - gi10*ui00 + c*ur10 - gi11*ui10;
            const float ni10 = gr10*ui00 + gi10*ur00 + c*ui10 + gi11*ur10;
            const float nr11 = gr10*ur01 - gi10*ui01 + c*ur11 - gi11*ui11;
            const float ni11 = gr10*ui01 + gi10*ur01 + c*ui11 + gi11*ur11;
            ur00 = nr00; ui00 = ni00; ur01 = nr01; ui01 = ni01;
            ur10 = nr10; ui10 = ni10; ur11 = nr11; ui11 = ni11;
        }
        const float m00  = ur00*ur00 + ui00*ui00 - (ur10*ur10 + ui10*ui10);
        const float m11  = ur01*ur01 + ui01*ui01 - (ur11*ur11 + ui11*ui11);
        const float m01r = (ur00*ur01 + ui00*ui01) - (ur10*ur11 + ui10*ui11);
        const float m01i = (ur00*ui01 - ui00*ur01) - (ur10*ui11 - ui10*ur11);
        const float h = hw[w];
        g1 = h * 0.5f * (m00 - m11);
        g2 = h * m01r;
        g3 = h * m01i;
        float c0w = h * 0.5f * (m00 + m11);
        c0w += __shfl_xor_sync(0xffffffffu, c0w, 1);
        c0w += __shfl_xor_sync(0xffffffffu, c0w, 2);
        Cc = hb[0] + c0w;
    }

    const float eb = enc_b[lane & 7];

    int sp = 0;
    for (int quad = warpId; quad < nQuads; quad += W) {
        CP_WAIT1();   // current stage landed

        const float4* sptr = dynbuf + ((sp * 8 + wIn) * 256) + lane;

        // rows 0,1 of the quad
        const float4 x0a = sptr[0],   x0b = sptr[32];
        const float4 x1a = sptr[64],  x1b = sptr[96];

        // prefetch quad+2W into the stage read LAST iteration
        {
            const int pf = quad + 2 * W;
            const int fs = (sp + 2 >= 3) ? sp - 1 : sp + 2;
            if (pf < nQuads) {
                const float4* g = x4 + (size_t)pf * 256 + lane;
                const unsigned d = sbase + (unsigned)fs * 32768u;
#pragma unroll
                for (int j = 0; j < 8; ++j) CP_ASYNC16(d + j * 512u, g + j * 32);
            }
            CP_COMMIT();
        }

        // ---- rows 0,1: accumulate then fold row-parity (lane bit 3) ----
        ull B01[4];
        {
            ull a0[4] = {0,0,0,0}, a1[4] = {0,0,0,0};
            const float xs0[8] = {x0a.x, x0a.y, x0a.z, x0a.w, x0b.x, x0b.y, x0b.z, x0b.w};
            const float xs1[8] = {x1a.x, x1a.y, x1a.z, x1a.w, x1b.x, x1b.y, x1b.z, x1b.w};
#pragma unroll
            for (int q = 0; q < 8; ++q) {
                const int c = q >> 2, j = q & 3;
                const ull xx0 = pack2(xs0[q], xs0[q]);
                const ull xx1 = pack2(xs1[q], xs1[q]);
#pragma unroll
                for (int p = 0; p < 4; ++p) {
                    a0[p] = fma2(xx0, wreg[p][c][j], a0[p]);
                    a1[p] = fma2(xx1, wreg[p][c][j], a1[p]);
                }
            }
#pragma unroll
            for (int p = 0; p < 4; ++p) {
                const ull mine  = (lane & 8) ? a1[p] : a0[p];
                const ull other = (lane & 8) ? a0[p] : a1[p];
                B01[p] = add2(mine, __shfl_xor_sync(0xffffffffu, other, 8));
            }
        }

        // ---- rows 2,3 ----
        const float4 x2a = sptr[128], x2b = sptr[160];
        const float4 x3a = sptr[192], x3b = sptr[224];
        ull B23[4];
        {
            ull a2[4] = {0,0,0,0}, a3[4] = {0,0,0,0};
            const float xs2[8] = {x2a.x, x2a.y, x2a.z, x2a.w, x2b.x, x2b.y, x2b.z, x2b.w};
            const float xs3[8] = {x3a.x, x3a.y, x3a.z, x3a.w, x3b.x, x3b.y, x3b.z, x3b.w};
#pragma unroll
            for (int q = 0; q < 8; ++q) {
                const int c = q >> 2, j = q & 3;
                const ull xx2 = pack2(xs2[q], xs2[q]);
                const ull xx3 = pack2(xs3[q], xs3[q]);
#pragma unroll
                for (int p = 0; p < 4; ++p) {
                    a2[p] = fma2(xx2, wreg[p][c][j], a2[p]);
                    a3[p] = fma2(xx3, wreg[p][c][j], a3[p]);
                }
            }
#pragma unroll
            for (int p = 0; p < 4; ++p) {
                const ull mine  = (lane & 8) ? a3[p] : a2[p];
                const ull other = (lane & 8) ? a2[p] : a3[p];
                B23[p] = add2(mine, __shfl_xor_sync(0xffffffffu, other, 8));
            }
        }

        // ---- remaining fold levels ----
        // xor16 (row high bit): bit4=0 keeps rows {0,1}, bit4=1 keeps {2,3}
        ull C[4];
#pragma unroll
        for (int p = 0; p < 4; ++p) {
            const ull mine  = (lane & 16) ? B23[p] : B01[p];
            const ull other = (lane & 16) ? B01[p] : B23[p];
            C[p] = add2(mine, __shfl_xor_sync(0xffffffffu, other, 16));
        }
        // xor4 (pair high bit)
        ull D0 = add2((lane & 4) ? C[2] : C[0],
                      __shfl_xor_sync(0xffffffffu, (lane & 4) ? C[0] : C[2], 4));
        ull D1 = add2((lane & 4) ? C[3] : C[1],
                      __shfl_xor_sync(0xffffffffu, (lane & 4) ? C[1] : C[3], 4));
        // xor2 (pair low bit)
        ull E = add2((lane & 2) ? D1 : D0,
                     __shfl_xor_sync(0xffffffffu, (lane & 2) ? D0 : D1, 2));
        // xor1 butterfly: both parity lanes get the pair sum
        E = add2(E, __shfl_xor_sync(0xffffffffu, E, 1));
        // lane L now holds pair (L>>1)&3 of row L>>3; parity bit selects elt:
        // j = (L&6)|(L&1) = L&7.

        // ---- shared epilogue: 8-lane group per row ----
        float dlo, dhi;
        unpack2(E, dlo, dhi);
        const float dj = (lane & 1) ? dhi : dlo;
        const float t = dj + eb;
        const float e = __expf(2.0f * t);              // tanh = 1 - 2/(e^2t+1)
        const float th = 1.0f - __fdividef(2.0f, e + 1.0f);
        float sn, cs;
        __sincosf(th, &sn, &cs);
        // RX lanes (j<4) pull RY trig from lane+4 (same row group)
        const float cb  = __shfl_sync(0xffffffffu, cs, lane + 4);
        const float sb2 = __shfl_sync(0xffffffffu, sn, lane + 4);
        float r = fmaf(cs, fmaf(g2, sb2, g1 * cb), g3 * sn);
        r += __shfl_xor_sync(0xffffffffu, r, 1);
        r += __shfl_xor_sync(0xffffffffu, r, 2);
        if ((lane & 7) == 0)
            out[4 * quad + (lane >> 3)] = r + Cc;

        sp = (sp + 1 >= 3) ? 0 : sp + 1;
    }
}

extern "C" void kernel_launch(void* const* d_in, const int* in_sizes, int n_in,
                              void* d_out, int out_size) {
    const float* x     = (const float*)d_in[0];
    const float* enc_w = (const float*)d_in[1];
    const float* enc_b = (const float*)d_in[2];
    const float* rp    = (const float*)d_in[3];
    const float* hw    = (const float*)d_in[4];
    const float* hb    = (const float*)d_in[5];
    float* out = (float*)d_out;

    const int B = in_sizes[0] / 256;  // F = 256

    const int SMEM = 3 * 8 * 256 * sizeof(float4);  // 96 KB
    cudaFuncSetAttribute(fused_kernel,
                         cudaFuncAttributeMaxDynamicSharedMemorySize, SMEM);
    fused_kernel<<<296, 256, SMEM>>>((const float4*)x, (const float4*)enc_w,
                                     enc_b, rp, hw, hb, out, B);
}